// round 2
// baseline (speedup 1.0000x reference)
#include <cuda_runtime.h>
#include <cuda_bf16.h>
#include <cstdint>

// ==========================================================================
// LORI_FC: out = x @ blockdiag(D) + (x @ Wl^T) @ Wr^T + (b_right + bias)
//   x [8192, 4096] f32, D [64, 64, 64], Wl [64, 4096], Wr [4096, 64]
// Split-bf16 (hi+lo, 3 passes) mma.sync.m16n8k16; fp32 accumulate.
//   K1: t = x @ Wl^T            (M=8192, N=64, K=4096)
//   K2: out tile = xb@D + t@Wr^T + bias   (per 128x64 tile)
// ==========================================================================

#define M_TOTAL 8192
#define IN_F    4096
#define OUT_F   4096
#define RANKD   64
#define PITCH   72   // bf16 elements per smem row (conflict-free: 36 words)

// scratch: t = x @ Wl^T  (8192 x 64 f32 = 2 MB)
__device__ __align__(16) float g_t[M_TOTAL * RANKD];

__device__ __forceinline__ void split2(float v, __nv_bfloat16* h, __nv_bfloat16* l) {
    __nv_bfloat16 hh = __float2bfloat16(v);
    *h = hh;
    *l = __float2bfloat16(v - __bfloat162float(hh));
}

#define MMA_BF16(C, A0, A1, A2, A3, B0, B1)                                   \
    asm volatile(                                                             \
        "mma.sync.aligned.m16n8k16.row.col.f32.bf16.bf16.f32 "                \
        "{%0,%1,%2,%3}, {%4,%5,%6,%7}, {%8,%9}, {%0,%1,%2,%3};"               \
        : "+f"((C)[0]), "+f"((C)[1]), "+f"((C)[2]), "+f"((C)[3])              \
        : "r"(A0), "r"(A1), "r"(A2), "r"(A3), "r"(B0), "r"(B1))

__device__ __forceinline__ uint32_t lds_u32(const __nv_bfloat16* p) {
    return *reinterpret_cast<const uint32_t*>(p);
}

// --------------------------------------------------------------------------
// K1: t = x @ Wl^T.  Grid 128 CTAs x 256 threads; 64 rows per CTA.
// K loop: 64 chunks of 64. Register-staged single smem buffer.
// --------------------------------------------------------------------------
__global__ void __launch_bounds__(256, 1)
k1_lowrank(const float* __restrict__ x, const float* __restrict__ wl) {
    __shared__ __align__(16) __nv_bfloat16 sAh[64 * PITCH];
    __shared__ __align__(16) __nv_bfloat16 sAl[64 * PITCH];
    __shared__ __align__(16) __nv_bfloat16 sBh[64 * PITCH];
    __shared__ __align__(16) __nv_bfloat16 sBl[64 * PITCH];

    const int tid = threadIdx.x;
    const int m0  = blockIdx.x * 64;
    const int lr  = tid >> 4;         // 0..15 (row base)
    const int lc  = tid & 15;         // 0..15 (float4 column)

    const int w    = tid >> 5;
    const int lane = tid & 31;
    const int g    = lane >> 2;
    const int q    = lane & 3;
    const int wm   = w >> 1;          // 0..3 -> row tile 16*wm
    const int wn   = w & 1;           // 0..1 -> col tile 32*wn

    float acc[4][4];
#pragma unroll
    for (int nf = 0; nf < 4; nf++)
#pragma unroll
        for (int i = 0; i < 4; i++) acc[nf][i] = 0.0f;

    float4 xr[4], wr[4];

    // prefetch chunk 0
#pragma unroll
    for (int f = 0; f < 4; f++) {
        xr[f] = *reinterpret_cast<const float4*>(&x[(size_t)(m0 + lr + 16 * f) * IN_F + lc * 4]);
        wr[f] = *reinterpret_cast<const float4*>(&wl[(size_t)(lr + 16 * f) * IN_F + lc * 4]);
    }

    for (int c = 0; c < 64; c++) {
        // stage regs -> smem (split hi/lo)
#pragma unroll
        for (int f = 0; f < 4; f++) {
            const float* vx = reinterpret_cast<const float*>(&xr[f]);
            const float* vw = reinterpret_cast<const float*>(&wr[f]);
            int r = lr + 16 * f;
#pragma unroll
            for (int i = 0; i < 4; i++) {
                split2(vx[i], &sAh[r * PITCH + lc * 4 + i], &sAl[r * PITCH + lc * 4 + i]);
                split2(vw[i], &sBh[r * PITCH + lc * 4 + i], &sBl[r * PITCH + lc * 4 + i]);
            }
        }
        __syncthreads();

        // prefetch next chunk while computing this one
        if (c < 63) {
            int kc = (c + 1) * 64;
#pragma unroll
            for (int f = 0; f < 4; f++) {
                xr[f] = *reinterpret_cast<const float4*>(&x[(size_t)(m0 + lr + 16 * f) * IN_F + kc + lc * 4]);
                wr[f] = *reinterpret_cast<const float4*>(&wl[(size_t)(lr + 16 * f) * IN_F + kc + lc * 4]);
            }
        }

        // compute: warp tile 16 x 32, K = 64 (4 sub-k of 16)
#pragma unroll
        for (int kk = 0; kk < 4; kk++) {
            const int k0 = kk * 16 + q * 2;
            const int ar = (wm * 16 + g) * PITCH;
            uint32_t ah0 = lds_u32(&sAh[ar + k0]);
            uint32_t ah1 = lds_u32(&sAh[ar + 8 * PITCH + k0]);
            uint32_t ah2 = lds_u32(&sAh[ar + k0 + 8]);
            uint32_t ah3 = lds_u32(&sAh[ar + 8 * PITCH + k0 + 8]);
            uint32_t al0 = lds_u32(&sAl[ar + k0]);
            uint32_t al1 = lds_u32(&sAl[ar + 8 * PITCH + k0]);
            uint32_t al2 = lds_u32(&sAl[ar + k0 + 8]);
            uint32_t al3 = lds_u32(&sAl[ar + 8 * PITCH + k0 + 8]);
#pragma unroll
            for (int nf = 0; nf < 4; nf++) {
                const int bn = (wn * 32 + nf * 8 + g) * PITCH;
                uint32_t bh0 = lds_u32(&sBh[bn + k0]);
                uint32_t bh1 = lds_u32(&sBh[bn + k0 + 8]);
                uint32_t bl0 = lds_u32(&sBl[bn + k0]);
                uint32_t bl1 = lds_u32(&sBl[bn + k0 + 8]);
                MMA_BF16(acc[nf], ah0, ah1, ah2, ah3, bh0, bh1);
                MMA_BF16(acc[nf], ah0, ah1, ah2, ah3, bl0, bl1);
                MMA_BF16(acc[nf], al0, al1, al2, al3, bh0, bh1);
            }
        }
        __syncthreads();
    }

    // epilogue: write t
#pragma unroll
    for (int nf = 0; nf < 4; nf++) {
        int row = m0 + wm * 16 + g;
        int col = wn * 32 + nf * 8 + q * 2;
        *reinterpret_cast<float2*>(&g_t[(size_t)row * RANKD + col]) =
            make_float2(acc[nf][0], acc[nf][1]);
        *reinterpret_cast<float2*>(&g_t[(size_t)(row + 8) * RANKD + col]) =
            make_float2(acc[nf][2], acc[nf][3]);
    }
}

// --------------------------------------------------------------------------
// K2: out[m0:m0+128, 64j:64j+64] = xb_j @ D_j + t @ Wr_j^T + (br + bias)
// Grid (64, 64), 256 threads, 2 CTAs/SM. Dynamic smem = 55296 B.
// --------------------------------------------------------------------------
__global__ void __launch_bounds__(256, 2)
k2_output(const float* __restrict__ x, const float* __restrict__ diag,
          const float* __restrict__ wrt, const float* __restrict__ br,
          const float* __restrict__ bias, float* __restrict__ out) {
    extern __shared__ __align__(16) __nv_bfloat16 sm[];
    __nv_bfloat16* sAh = sm;                         // 128*PITCH
    __nv_bfloat16* sAl = sAh + 128 * PITCH;
    __nv_bfloat16* sBh = sAl + 128 * PITCH;          // 64*PITCH
    __nv_bfloat16* sBl = sBh + 64 * PITCH;

    const int tid = threadIdx.x;
    const int m0  = blockIdx.x * 128;
    const int j   = blockIdx.y;
    const int lr  = tid >> 4;
    const int lc  = tid & 15;

    const int w    = tid >> 5;        // 0..7 -> row tile 16*w
    const int lane = tid & 31;
    const int g    = lane >> 2;
    const int q    = lane & 3;

    float acc[8][4];
#pragma unroll
    for (int nf = 0; nf < 8; nf++)
#pragma unroll
        for (int i = 0; i < 4; i++) acc[nf][i] = 0.0f;

    // ---------------- phase 1: A = xb (128x64), B = D_j^T ----------------
#pragma unroll
    for (int f = 0; f < 8; f++) {
        int r = lr + 16 * f;
        float4 v = *reinterpret_cast<const float4*>(
            &x[(size_t)(m0 + r) * IN_F + j * 64 + lc * 4]);
        const float* vp = reinterpret_cast<const float*>(&v);
#pragma unroll
        for (int i = 0; i < 4; i++)
            split2(vp[i], &sAh[r * PITCH + lc * 4 + i], &sAl[r * PITCH + lc * 4 + i]);
    }
#pragma unroll
    for (int f = 0; f < 4; f++) {
        int k = lr + 16 * f;                 // row of D (input dim)
        float4 v = *reinterpret_cast<const float4*>(
            &diag[(size_t)j * 4096 + (size_t)k * 64 + lc * 4]);
        const float* vp = reinterpret_cast<const float*>(&v);
#pragma unroll
        for (int i = 0; i < 4; i++) {        // transpose: B[n][k] = D[k][n]
            int n = lc * 4 + i;
            split2(vp[i], &sBh[n * PITCH + k], &sBl[n * PITCH + k]);
        }
    }
    __syncthreads();

#pragma unroll
    for (int kk = 0; kk < 4; kk++) {
        const int k0 = kk * 16 + q * 2;
        const int ar = (w * 16 + g) * PITCH;
        uint32_t ah0 = lds_u32(&sAh[ar + k0]);
        uint32_t ah1 = lds_u32(&sAh[ar + 8 * PITCH + k0]);
        uint32_t ah2 = lds_u32(&sAh[ar + k0 + 8]);
        uint32_t ah3 = lds_u32(&sAh[ar + 8 * PITCH + k0 + 8]);
        uint32_t al0 = lds_u32(&sAl[ar + k0]);
        uint32_t al1 = lds_u32(&sAl[ar + 8 * PITCH + k0]);
        uint32_t al2 = lds_u32(&sAl[ar + k0 + 8]);
        uint32_t al3 = lds_u32(&sAl[ar + 8 * PITCH + k0 + 8]);
#pragma unroll
        for (int nf = 0; nf < 8; nf++) {
            const int bn = (nf * 8 + g) * PITCH;
            uint32_t bh0 = lds_u32(&sBh[bn + k0]);
            uint32_t bh1 = lds_u32(&sBh[bn + k0 + 8]);
            uint32_t bl0 = lds_u32(&sBl[bn + k0]);
            uint32_t bl1 = lds_u32(&sBl[bn + k0 + 8]);
            MMA_BF16(acc[nf], ah0, ah1, ah2, ah3, bh0, bh1);
            MMA_BF16(acc[nf], ah0, ah1, ah2, ah3, bl0, bl1);
            MMA_BF16(acc[nf], al0, al1, al2, al3, bh0, bh1);
        }
    }
    __syncthreads();

    // ---------------- phase 2: A = t (128x64), B = Wr_j (64x64) ----------
#pragma unroll
    for (int f = 0; f < 8; f++) {
        int r = lr + 16 * f;
        float4 v = *reinterpret_cast<const float4*>(
            &g_t[(size_t)(m0 + r) * RANKD + lc * 4]);
        const float* vp = reinterpret_cast<const float*>(&v);
#pragma unroll
        for (int i = 0; i < 4; i++)
            split2(vp[i], &sAh[r * PITCH + lc * 4 + i], &sAl[r * PITCH + lc * 4 + i]);
    }
#pragma unroll
    for (int f = 0; f < 4; f++) {
        int n = lr + 16 * f;                 // output col within block
        float4 v = *reinterpret_cast<const float4*>(
            &wrt[(size_t)(j * 64 + n) * RANKD + lc * 4]);
        const float* vp = reinterpret_cast<const float*>(&v);
#pragma unroll
        for (int i = 0; i < 4; i++)          // Wr is [n][k] already
            split2(vp[i], &sBh[n * PITCH + lc * 4 + i], &sBl[n * PITCH + lc * 4 + i]);
    }
    __syncthreads();

#pragma unroll
    for (int kk = 0; kk < 4; kk++) {
        const int k0 = kk * 16 + q * 2;
        const int ar = (w * 16 + g) * PITCH;
        uint32_t ah0 = lds_u32(&sAh[ar + k0]);
        uint32_t ah1 = lds_u32(&sAh[ar + 8 * PITCH + k0]);
        uint32_t ah2 = lds_u32(&sAh[ar + k0 + 8]);
        uint32_t ah3 = lds_u32(&sAh[ar + 8 * PITCH + k0 + 8]);
        uint32_t al0 = lds_u32(&sAl[ar + k0]);
        uint32_t al1 = lds_u32(&sAl[ar + 8 * PITCH + k0]);
        uint32_t al2 = lds_u32(&sAl[ar + k0 + 8]);
        uint32_t al3 = lds_u32(&sAl[ar + 8 * PITCH + k0 + 8]);
#pragma unroll
        for (int nf = 0; nf < 8; nf++) {
            const int bn = (nf * 8 + g) * PITCH;
            uint32_t bh0 = lds_u32(&sBh[bn + k0]);
            uint32_t bh1 = lds_u32(&sBh[bn + k0 + 8]);
            uint32_t bl0 = lds_u32(&sBl[bn + k0]);
            uint32_t bl1 = lds_u32(&sBl[bn + k0 + 8]);
            MMA_BF16(acc[nf], ah0, ah1, ah2, ah3, bh0, bh1);
            MMA_BF16(acc[nf], ah0, ah1, ah2, ah3, bl0, bl1);
            MMA_BF16(acc[nf], al0, al1, al2, al3, bh0, bh1);
        }
    }

    // ---------------- epilogue: + b_right + bias ----------------
#pragma unroll
    for (int nf = 0; nf < 8; nf++) {
        int col = nf * 8 + q * 2;
        int gc  = j * 64 + col;
        float b0 = br[gc] + bias[gc];
        float b1 = br[gc + 1] + bias[gc + 1];
        int row = m0 + w * 16 + g;
        *reinterpret_cast<float2*>(&out[(size_t)row * OUT_F + gc]) =
            make_float2(acc[nf][0] + b0, acc[nf][1] + b1);
        *reinterpret_cast<float2*>(&out[(size_t)(row + 8) * OUT_F + gc]) =
            make_float2(acc[nf][2] + b0, acc[nf][3] + b1);
    }
}

// --------------------------------------------------------------------------
extern "C" void kernel_launch(void* const* d_in, const int* in_sizes, int n_in,
                              void* d_out, int out_size) {
    const float* x    = (const float*)d_in[0];
    const float* diag = (const float*)d_in[1];
    const float* wl   = (const float*)d_in[2];
    const float* wrt  = (const float*)d_in[3];
    const float* br   = (const float*)d_in[4];
    const float* bias = (const float*)d_in[5];
    float* out = (float*)d_out;

    const int smem_k2 = (128 * PITCH * 2 + 64 * PITCH * 2) * (int)sizeof(__nv_bfloat16);
    cudaFuncSetAttribute(k2_output, cudaFuncAttributeMaxDynamicSharedMemorySize, smem_k2);

    k1_lowrank<<<128, 256>>>(x, wl);
    k2_output<<<dim3(64, 64), 256, smem_k2>>>(x, diag, wrt, br, bias, out);
}